// round 13
// baseline (speedup 1.0000x reference)
#include <cuda_runtime.h>
#include <cstdint>

// DTree_84061099917446 — soft decision tree forward pass.
// N=262144 rows, F=32, depth 8, 255 nodes, 256 leaves, C=1.
//
// R13: R12 regressed because producer A-loads were raw GMEM LDGs consumed
// immediately (exposed ~600cyc/m-step; every pipe idle). Fix: (a) prep2
// kernel pre-splits X into bf16 hi/lo pairs in GMEM scratch once (~9us);
// (b) cp.async double-buffers the 10.7KB X tile one full pipeline phase
// ahead (row stride 168B -> fragment LDS.64 conflict-free); (c) producer
// steady-state touches only smem/regs: LDS A-frags, reg-resident B/bias
// (R12), bf16 4-pass mma.sync (R12, rel_err 6.6e-7), STS z. Consumers
// (8 warps) walk the tree from double-buffered z as in R11/R12.

#define F_        32
#define NODES_    255
#define N_ROWS    262144
#define ROWS_T    64
#define NTILES    (N_ROWS / ROWS_T)     // 4096
#define TPB       512
#define GRID_     148
#define LOG2E_F   1.4426950408889634f

typedef unsigned int u32;
typedef unsigned long long u64;

// ---- smem layout (byte offsets) ----
#define ZSTR      257                    // floats; odd -> conflict-free walk
#define XSTR      168                    // bytes/row; 21*gid+2*tig inj. mod 32
#define SM_Z0     0                      // 64*257*4 = 65792
#define SM_Z1     65792
#define SM_X0     131584                 // 64*168 = 10752
#define SM_X1     142336
#define SM_PR     153088                 // 128 float2
#define SM_PBUF   154112                 // 256 floats
#define SM_TOTAL  155136

// Prologue outputs (scratch via __device__ globals — no allocation).
__device__ __align__(16) float4 g_Bh4[1024];   // B frags bf16x2 hi (mma order)
__device__ __align__(16) float4 g_Bl4[1024];   // B frags bf16x2 lo
__device__ float  g_bias[256];                 // +log2e*c (idx 255: 0)
__device__ float2 g_pr[128];                   // (clsR, clsL - clsR)
__device__ __align__(16) u64 g_Xp[(size_t)N_ROWS * 16];  // (hi,lo) per kpair, 32MB

// ---------------------------------------------------------------------------
// split float2 -> bf16x2 hi (truncate) + bf16x2 lo (residual, rn)
__device__ __forceinline__ void split2(float vx, float vy, u32& hi, u32& lo) {
    u32 bx = __float_as_uint(vx), by = __float_as_uint(vy);
    hi = __byte_perm(bx, by, 0x7632);
    float lx = vx - __uint_as_float(bx & 0xFFFF0000u);
    float ly = vy - __uint_as_float(by & 0xFFFF0000u);
    asm("cvt.rn.bf16x2.f32 %0, %1, %2;" : "=r"(lo) : "f"(ly), "f"(lx));
}

// ---------------------------------------------------------------------------
// Prologue 1: W frags (bf16 hi/lo, m16n8k16 B-fragment order), bias, pairs.
// One block, 256 threads; thread t = node t (255 = zero pad). (R12, verified)
// ---------------------------------------------------------------------------
__global__ void prep_kernel(const float* __restrict__ fi,
                            const float* __restrict__ fs,
                            const float* __restrict__ cls) {
    int t = threadIdx.x;
    if (t < 256) {
        float wp[F_];
        float bias = 0.0f;
        #pragma unroll
        for (int f = 0; f < F_; ++f) {
            float v = 0.0f;
            if (t < NODES_) {
                int idx = t * F_ + f;
                float w = fmaxf(fi[idx], 0.0f);
                float s = 1.0f / (1.0f + expf(-fs[idx]));
                bias += w * s;
                v = -LOG2E_F * w;
            }
            wp[f] = v;
        }
        int cidx = t >> 3, gcol = t & 7;
        #pragma unroll
        for (int tig = 0; tig < 4; ++tig) {
            u32 qh[4], ql[4];
            #pragma unroll
            for (int s = 0; s < 2; ++s)
                #pragma unroll
                for (int r = 0; r < 2; ++r) {
                    int k = 16 * s + 8 * r + 2 * tig;
                    split2(wp[k], wp[k + 1], qh[s * 2 + r], ql[s * 2 + r]);
                }
            int base = cidx * 32 + gcol * 4 + tig;
            g_Bh4[base] = make_float4(__uint_as_float(qh[0]), __uint_as_float(qh[1]),
                                      __uint_as_float(qh[2]), __uint_as_float(qh[3]));
            g_Bl4[base] = make_float4(__uint_as_float(ql[0]), __uint_as_float(ql[1]),
                                      __uint_as_float(ql[2]), __uint_as_float(ql[3]));
        }
        g_bias[t] = (t < NODES_) ? (LOG2E_F * bias) : 0.0f;
    }
    if (t < 128) {
        float lv = cls[2 * t];
        float rv = cls[2 * t + 1];
        g_pr[t] = make_float2(rv, lv - rv);
    }
}

// ---------------------------------------------------------------------------
// Prologue 2: split all of X into (hi,lo) bf16x2 per feature-pair. Coalesced.
// ---------------------------------------------------------------------------
__global__ void prep_x(const float* __restrict__ x) {
    size_t i = (size_t)blockIdx.x * blockDim.x + threadIdx.x;  // row*16+kp
    float2 v = reinterpret_cast<const float2*>(x)[i];
    u32 hi, lo;
    split2(v.x, v.y, hi, lo);
    g_Xp[i] = (u64)hi | ((u64)lo << 32);      // [addr]=hi, [addr+4]=lo
}

// ---------------------------------------------------------------------------
__device__ __forceinline__ u32 smem_u32(const void* p) {
    u32 a;
    asm("{ .reg .u64 t; cvta.to.shared.u64 t, %1; cvt.u32.u64 %0, t; }"
        : "=r"(a) : "l"(p));
    return a;
}

__device__ __forceinline__ void cp_async8(u32 dst, const void* src) {
    u64 gsrc;
    asm("cvta.to.global.u64 %0, %1;" : "=l"(gsrc) : "l"(src));
    asm volatile("cp.async.ca.shared.global [%0], [%1], 8;"
                 :: "r"(dst), "l"(gsrc) : "memory");
}
#define CP_COMMIT()  asm volatile("cp.async.commit_group;" ::: "memory")
#define CP_WAIT1()   asm volatile("cp.async.wait_group 1;" ::: "memory")

__device__ __forceinline__ void mma16(float (&d)[4], const u32* a,
                                      u32 b0, u32 b1) {
    asm volatile(
        "mma.sync.aligned.m16n8k16.row.col.f32.bf16.bf16.f32 "
        "{%0,%1,%2,%3}, {%4,%5,%6,%7}, {%8,%9}, {%0,%1,%2,%3};"
        : "+f"(d[0]), "+f"(d[1]), "+f"(d[2]), "+f"(d[3])
        : "r"(a[0]), "r"(a[1]), "r"(a[2]), "r"(a[3]), "r"(b0), "r"(b1));
}

__device__ __forceinline__ float fgate(float y) {   // 1 / (1 + 2^y)
    float e, g;
    asm("ex2.approx.f32 %0, %1;" : "=f"(e) : "f"(y));
    float d = 1.0f + e;
    asm("rcp.approx.f32 %0, %1;" : "=f"(g) : "f"(d));
    return g;
}

#define CTA_BAR()   asm volatile("barrier.sync 0;" ::: "memory")
#define EPI_BAR()   asm volatile("barrier.sync 1, 256;" ::: "memory")
#define PROD_BAR()  asm volatile("barrier.sync 2, 256;" ::: "memory")

// ---------------------------------------------------------------------------
template<int DEPTH, int NODE>
__device__ __forceinline__ void walk(const float*  __restrict__ zr,
                                     const float2* __restrict__ spr,
                                     float prod, float& acc) {
    float g = fgate(zr[NODE]);
    if constexpr (DEPTH == 7) {
        float2 pr = spr[NODE - 127];
        acc = fmaf(prod, fmaf(g, pr.y, pr.x), acc);
    } else {
        float r = fmaf(-prod, g, prod);
        walk<DEPTH + 1, 2 * NODE + 1>(zr, spr, prod * g, acc);
        walk<DEPTH + 1, 2 * NODE + 2>(zr, spr, r, acc);
    }
}

// ---------------------------------------------------------------------------
__global__ void __launch_bounds__(TPB, 1)
dtree_kernel(float* __restrict__ out) {
    extern __shared__ __align__(16) char smem[];
    float2* spr  = reinterpret_cast<float2*>(smem + SM_PR);
    float*  pbuf = reinterpret_cast<float*>(smem + SM_PBUF);
    u32 sbase = smem_u32(smem);

    int tid  = threadIdx.x;
    int lane = tid & 31;
    int wrp  = tid >> 5;
    int bid  = blockIdx.x;
    int nblk = (NTILES - bid + GRID_ - 1) / GRID_;

    if (tid < 128) spr[tid] = g_pr[tid];   // published by first CTA_BAR

    if (wrp < 8) {
        // ============ producers ============
        int gid = lane >> 2, tig = lane & 3;

        // B + bias resident in registers (one-time GMEM read).
        u32 bh[16], bl[16];
        float2 bias2[4];
        #pragma unroll
        for (int nt = 0; nt < 4; ++nt) {
            float4 h = __ldg(&g_Bh4[(wrp * 4 + nt) * 32 + lane]);
            float4 l = __ldg(&g_Bl4[(wrp * 4 + nt) * 32 + lane]);
            bh[nt * 4]     = __float_as_uint(h.x);
            bh[nt * 4 + 1] = __float_as_uint(h.y);
            bh[nt * 4 + 2] = __float_as_uint(h.z);
            bh[nt * 4 + 3] = __float_as_uint(h.w);
            bl[nt * 4]     = __float_as_uint(l.x);
            bl[nt * 4 + 1] = __float_as_uint(l.y);
            bl[nt * 4 + 2] = __float_as_uint(l.z);
            bl[nt * 4 + 3] = __float_as_uint(l.w);
            bias2[nt] = *reinterpret_cast<const float2*>(
                g_bias + wrp * 32 + nt * 8 + 2 * tig);
        }

        // prologue: stage tile for step 0 into X0
        {
            const u64* src = g_Xp + (size_t)bid * 1024;
            #pragma unroll
            for (int q = 0; q < 4; ++q) {
                int c = tid + q * 256;          // 0..1023
                int row = c >> 4, kp = c & 15;
                cp_async8(sbase + SM_X0 + row * XSTR + kp * 8, src + c);
            }
            CP_COMMIT();
        }

        for (int step = 0; step <= nblk; ++step) {
            CTA_BAR();
            if (step >= nblk) continue;
            int tile = bid + step * GRID_;
            float* sz = reinterpret_cast<float*>(
                smem + ((step & 1) ? SM_Z1 : SM_Z0));
            u32 xb = sbase + ((step & 1) ? SM_X1 : SM_X0);
            u32 xbn = sbase + ((step & 1) ? SM_X0 : SM_X1);

            // prefetch tile step+1 (clamped; dead copy on last step)
            {
                int tn = tile + GRID_;
                if (tn >= NTILES) tn = tile;
                const u64* src = g_Xp + (size_t)tn * 1024;
                #pragma unroll
                for (int q = 0; q < 4; ++q) {
                    int c = tid + q * 256;
                    int row = c >> 4, kp = c & 15;
                    cp_async8(xbn + row * XSTR + kp * 8, src + c);
                }
                CP_COMMIT();
            }
            CP_WAIT1();     // own copies of current tile done
            PROD_BAR();     // all producers' copies done -> tile visible

            #pragma unroll
            for (int m = 0; m < 4; ++m) {
                int r0 = m * 16 + gid;
                u32 ah[8], al[8];
                #pragma unroll
                for (int s = 0; s < 2; ++s)
                    #pragma unroll
                    for (int p = 0; p < 2; ++p) {
                        int kp = tig + 4 * p + 8 * s;
                        int ix = s * 4 + p * 2;
                        asm volatile("ld.shared.v2.u32 {%0, %1}, [%2];"
                            : "=r"(ah[ix]), "=r"(al[ix])
                            : "r"(xb + r0 * XSTR + kp * 8));
                        asm volatile("ld.shared.v2.u32 {%0, %1}, [%2];"
                            : "=r"(ah[ix + 1]), "=r"(al[ix + 1])
                            : "r"(xb + (r0 + 8) * XSTR + kp * 8));
                    }
                #pragma unroll
                for (int nt = 0; nt < 4; ++nt) {
                    float d[4]  = {bias2[nt].x, bias2[nt].y,
                                   bias2[nt].x, bias2[nt].y};
                    float e[4]  = {0.f, 0.f, 0.f, 0.f};
                    float f4[4] = {0.f, 0.f, 0.f, 0.f};
                    #pragma unroll
                    for (int s = 0; s < 2; ++s) {
                        u32 b0h = bh[nt * 4 + s * 2], b1h = bh[nt * 4 + s * 2 + 1];
                        u32 b0l = bl[nt * 4 + s * 2], b1l = bl[nt * 4 + s * 2 + 1];
                        mma16(d,  &ah[s * 4], b0h, b1h);   // hi*hi (+bias)
                        mma16(e,  &ah[s * 4], b0l, b1l);   // hi*lo
                        mma16(e,  &al[s * 4], b0h, b1h);   // lo*hi
                        mma16(f4, &al[s * 4], b0l, b1l);   // lo*lo
                    }
                    int c0 = wrp * 32 + nt * 8 + 2 * tig;
                    float* z0 = sz + r0 * ZSTR + c0;
                    float* z1 = sz + (r0 + 8) * ZSTR + c0;
                    z0[0] = d[0] + e[0] + f4[0];
                    z0[1] = d[1] + e[1] + f4[1];
                    z1[0] = d[2] + e[2] + f4[2];
                    z1[1] = d[3] + e[3] + f4[3];
                }
            }
        }
    } else {
        // ============ consumers: tree walk ============
        int etid = tid - 256;
        int row  = etid & 63;
        int j    = etid >> 6;
        for (int step = 0; step <= nblk; ++step) {
            CTA_BAR();
            if (step < 1) continue;
            int tile = bid + (step - 1) * GRID_;
            const float* sz = reinterpret_cast<const float*>(
                smem + (((step - 1) & 1) ? SM_Z1 : SM_Z0));
            const float* zr = sz + row * ZSTR;

            float g0 = fgate(zr[0]);
            float ga = fgate(zr[1 + (j >> 1)]);
            float p1 = (j & 2) ? (1.0f - g0) : g0;
            float p2 = (j & 1) ? (1.0f - ga) : ga;
            float prod = p1 * p2;
            float acc = 0.0f;
            switch (j) {
                case 0:  walk<2, 3>(zr, spr, prod, acc); break;
                case 1:  walk<2, 4>(zr, spr, prod, acc); break;
                case 2:  walk<2, 5>(zr, spr, prod, acc); break;
                default: walk<2, 6>(zr, spr, prod, acc); break;
            }
            pbuf[etid] = acc;
            EPI_BAR();
            if (j == 0) {
                float s = (pbuf[row] + pbuf[row + 64]) +
                          (pbuf[row + 128] + pbuf[row + 192]);
                out[tile * ROWS_T + row] = s;
            }
        }
    }
}

// ---------------------------------------------------------------------------
extern "C" void kernel_launch(void* const* d_in, const int* in_sizes, int n_in,
                              void* d_out, int out_size) {
    const float* x   = (const float*)d_in[0];   // (N, 32)
    const float* fi  = (const float*)d_in[1];   // (255*32, 1)
    const float* fs  = (const float*)d_in[2];   // (255*32, 1)
    const float* cls = (const float*)d_in[3];   // (256, 1)
    float* out = (float*)d_out;                 // (N, 1) float32

    cudaFuncSetAttribute(dtree_kernel,
                         cudaFuncAttributeMaxDynamicSharedMemorySize, SM_TOTAL);
    prep_kernel<<<1, 256>>>(fi, fs, cls);
    prep_x<<<(N_ROWS * 16) / 256, 256>>>(x);
    dtree_kernel<<<GRID_, TPB, SM_TOTAL>>>(out);
}

// round 14
// speedup vs baseline: 1.2010x; 1.2010x over previous
#include <cuda_runtime.h>
#include <cstdint>

// DTree_84061099917446 — soft decision tree forward pass.
// N=262144 rows, F=32, depth 8, 255 nodes, 256 leaves, C=1.
//
// R14: 2 CTAs/SM. R10-R13 all sat at ~150-190us with every pipe <35% busy:
// with 1 CTA/SM the lockstep producer/consumer pipeline has nothing to
// absorb latency/barrier skew. Now: 256-thread CTAs (4 producer + 4
// consumer warps), 32-row tiles, 69KB smem, grid 296 -> 2 co-resident
// pipelines per SM. GEMM = mma.sync.m16n8k16.bf16 3-pass hi/lo (drop lo*lo,
// err ~1e-5), B frags + A direct-LDG in regs, bias via broadcast LDS.
// prep rewritten 256x32 warp-parallel (~3us, was 14); prep_x dropped.

#define F_        32
#define NODES_    255
#define N_ROWS    262144
#define ROWS_T    32
#define NTILES    (N_ROWS / ROWS_T)     // 8192
#define TPB       256
#define NCTA      296
#define LOG2E_F   1.4426950408889634f

typedef unsigned int u32;
typedef unsigned long long u64;

// ---- smem layout (byte offsets) ----
#define ZSTR      261                    // mod 32 = 5: consumer conflict-free
#define SM_Z0     0                      // 32*261*4 = 33408
#define SM_Z1     33408
#define SM_BIAS   66816                  // 256 floats
#define SM_PR     67840                  // 128 float2
#define SM_PBUF   68864                  // 128 floats
#define SM_TOTAL  69376

// Prologue outputs (scratch via __device__ globals — no allocation).
__device__ __align__(16) float4 g_Bh4[1024];   // B frags bf16x2 hi (mma order)
__device__ __align__(16) float4 g_Bl4[1024];   // B frags bf16x2 lo
__device__ float  g_bias[256];                 // +log2e*c (idx 255: 0)
__device__ float2 g_pr[128];                   // (clsR, clsL - clsR)

// ---------------------------------------------------------------------------
// split (x,y) -> bf16x2 hi (truncate) + bf16x2 lo (residual, rn)
__device__ __forceinline__ void split2(float vx, float vy, u32& hi, u32& lo) {
    u32 bx = __float_as_uint(vx), by = __float_as_uint(vy);
    hi = __byte_perm(bx, by, 0x7632);
    float lx = vx - __uint_as_float(bx & 0xFFFF0000u);
    float ly = vy - __uint_as_float(by & 0xFFFF0000u);
    asm("cvt.rn.bf16x2.f32 %0, %1, %2;" : "=r"(lo) : "f"(ly), "f"(lx));
}

// ---------------------------------------------------------------------------
// Prologue: 256 blocks x 32 threads; block n = node/column n (255 = pad).
// ---------------------------------------------------------------------------
__global__ void prep_kernel(const float* __restrict__ fi,
                            const float* __restrict__ fs,
                            const float* __restrict__ cls) {
    __shared__ float sh[F_];
    int n = blockIdx.x;
    int f = threadIdx.x;
    float w = 0.0f, s = 0.0f;
    if (n < NODES_) {
        int idx = n * F_ + f;
        w = fmaxf(fi[idx], 0.0f);
        s = 1.0f / (1.0f + expf(-fs[idx]));
    }
    sh[f] = -LOG2E_F * w;
    float p = w * s;
    #pragma unroll
    for (int o = 16; o > 0; o >>= 1) p += __shfl_xor_sync(0xffffffffu, p, o);
    __syncwarp();
    if (f == 0) g_bias[n] = (n < NODES_) ? (LOG2E_F * p) : 0.0f;
    if (f < 4) {
        int tig = f;
        u32 qh[4], ql[4];
        #pragma unroll
        for (int s2 = 0; s2 < 2; ++s2)
            #pragma unroll
            for (int r = 0; r < 2; ++r) {
                int k = 16 * s2 + 8 * r + 2 * tig;
                split2(sh[k], sh[k + 1], qh[s2 * 2 + r], ql[s2 * 2 + r]);
            }
        int base = (n >> 3) * 32 + (n & 7) * 4 + tig;
        g_Bh4[base] = make_float4(__uint_as_float(qh[0]), __uint_as_float(qh[1]),
                                  __uint_as_float(qh[2]), __uint_as_float(qh[3]));
        g_Bl4[base] = make_float4(__uint_as_float(ql[0]), __uint_as_float(ql[1]),
                                  __uint_as_float(ql[2]), __uint_as_float(ql[3]));
    }
    if (n < 128 && f == 0) {
        float lv = cls[2 * n];
        float rv = cls[2 * n + 1];
        g_pr[n] = make_float2(rv, lv - rv);
    }
}

// ---------------------------------------------------------------------------
__device__ __forceinline__ void mma16(float (&d)[4], const u32* a,
                                      u32 b0, u32 b1) {
    asm volatile(
        "mma.sync.aligned.m16n8k16.row.col.f32.bf16.bf16.f32 "
        "{%0,%1,%2,%3}, {%4,%5,%6,%7}, {%8,%9}, {%0,%1,%2,%3};"
        : "+f"(d[0]), "+f"(d[1]), "+f"(d[2]), "+f"(d[3])
        : "r"(a[0]), "r"(a[1]), "r"(a[2]), "r"(a[3]), "r"(b0), "r"(b1));
}

__device__ __forceinline__ float fgate(float y) {   // 1 / (1 + 2^y)
    float e, g;
    asm("ex2.approx.f32 %0, %1;" : "=f"(e) : "f"(y));
    float d = 1.0f + e;
    asm("rcp.approx.f32 %0, %1;" : "=f"(g) : "f"(d));
    return g;
}

#define CTA_BAR()  asm volatile("barrier.sync 0;" ::: "memory")
#define EPI_BAR()  asm volatile("barrier.sync 1, 128;" ::: "memory")

// ---------------------------------------------------------------------------
template<int DEPTH, int NODE>
__device__ __forceinline__ void walk(const float*  __restrict__ zr,
                                     const float2* __restrict__ spr,
                                     float prod, float& acc) {
    float g = fgate(zr[NODE]);
    if constexpr (DEPTH == 7) {
        float2 pr = spr[NODE - 127];
        acc = fmaf(prod, fmaf(g, pr.y, pr.x), acc);
    } else {
        float r = fmaf(-prod, g, prod);
        walk<DEPTH + 1, 2 * NODE + 1>(zr, spr, prod * g, acc);
        walk<DEPTH + 1, 2 * NODE + 2>(zr, spr, r, acc);
    }
}

// ---------------------------------------------------------------------------
__global__ void __launch_bounds__(TPB, 2)
dtree_kernel(const float* __restrict__ x,
             float* __restrict__ out) {
    extern __shared__ __align__(16) char smem[];
    float*  sbias = reinterpret_cast<float*>(smem + SM_BIAS);
    float2* spr   = reinterpret_cast<float2*>(smem + SM_PR);
    float*  pbuf  = reinterpret_cast<float*>(smem + SM_PBUF);

    int tid  = threadIdx.x;
    int lane = tid & 31;
    int wrp  = tid >> 5;
    int bid  = blockIdx.x;
    int nblk = (NTILES - bid + NCTA - 1) / NCTA;

    sbias[tid] = g_bias[tid];              // published by first CTA_BAR
    if (tid < 128) spr[tid] = g_pr[tid];

    if (wrp < 4) {
        // ============ producers: bf16 3-pass GEMM, 64 cols/warp ============
        int gid = lane >> 2, tig = lane & 3;

        u32 bh[32], bl[32];                // [nt*4 + s*2 + r], nt = 0..7
        #pragma unroll
        for (int nt = 0; nt < 8; ++nt) {
            float4 h = __ldg(&g_Bh4[(wrp * 8 + nt) * 32 + lane]);
            float4 l = __ldg(&g_Bl4[(wrp * 8 + nt) * 32 + lane]);
            bh[nt * 4]     = __float_as_uint(h.x);
            bh[nt * 4 + 1] = __float_as_uint(h.y);
            bh[nt * 4 + 2] = __float_as_uint(h.z);
            bh[nt * 4 + 3] = __float_as_uint(h.w);
            bl[nt * 4]     = __float_as_uint(l.x);
            bl[nt * 4 + 1] = __float_as_uint(l.y);
            bl[nt * 4 + 2] = __float_as_uint(l.z);
            bl[nt * 4 + 3] = __float_as_uint(l.w);
        }

        for (int step = 0; step <= nblk; ++step) {
            CTA_BAR();
            if (step >= nblk) continue;
            int tile = bid + step * NCTA;
            float* sz = reinterpret_cast<float*>(
                smem + ((step & 1) ? SM_Z1 : SM_Z0));
            const float2* xt2 =
                reinterpret_cast<const float2*>(x) + (size_t)tile * 512;

            #pragma unroll
            for (int m = 0; m < 2; ++m) {
                int r0 = m * 16 + gid;
                // A loads (issued up front), then split
                float2 v0[4], v1[4];
                #pragma unroll
                for (int s2 = 0; s2 < 2; ++s2)
                    #pragma unroll
                    for (int p = 0; p < 2; ++p) {
                        int kp = tig + 4 * p + 8 * s2;
                        int ix = s2 * 2 + p;
                        v0[ix] = __ldg(&xt2[r0 * 16 + kp]);
                        v1[ix] = __ldg(&xt2[(r0 + 8) * 16 + kp]);
                    }
                u32 ah[8], al[8];
                #pragma unroll
                for (int s2 = 0; s2 < 2; ++s2)
                    #pragma unroll
                    for (int p = 0; p < 2; ++p) {
                        int ix = s2 * 4 + p * 2;
                        int iv = s2 * 2 + p;
                        split2(v0[iv].x, v0[iv].y, ah[ix],     al[ix]);
                        split2(v1[iv].x, v1[iv].y, ah[ix + 1], al[ix + 1]);
                    }
                #pragma unroll
                for (int nt = 0; nt < 8; ++nt) {
                    int c0 = wrp * 64 + nt * 8 + 2 * tig;
                    float2 bi = *reinterpret_cast<const float2*>(sbias + c0);
                    float d[4] = {bi.x, bi.y, bi.x, bi.y};
                    float e[4] = {0.f, 0.f, 0.f, 0.f};
                    #pragma unroll
                    for (int s2 = 0; s2 < 2; ++s2) {
                        u32 b0h = bh[nt * 4 + s2 * 2];
                        u32 b1h = bh[nt * 4 + s2 * 2 + 1];
                        u32 b0l = bl[nt * 4 + s2 * 2];
                        u32 b1l = bl[nt * 4 + s2 * 2 + 1];
                        mma16(d, &ah[s2 * 4], b0h, b1h);   // hi*hi (+bias)
                        mma16(e, &ah[s2 * 4], b0l, b1l);   // hi*lo
                        mma16(e, &al[s2 * 4], b0h, b1h);   // lo*hi
                    }
                    float* z0 = sz + r0 * ZSTR + c0;
                    float* z1 = sz + (r0 + 8) * ZSTR + c0;
                    z0[0] = d[0] + e[0];
                    z0[1] = d[1] + e[1];
                    z1[0] = d[2] + e[2];
                    z1[1] = d[3] + e[3];
                }
            }
        }
    } else {
        // ============ consumers: tree walk ============
        int etid = tid - 128;
        int row  = etid & 31;
        int j    = etid >> 5;
        for (int step = 0; step <= nblk; ++step) {
            CTA_BAR();
            if (step < 1) continue;
            int tile = bid + (step - 1) * NCTA;
            const float* sz = reinterpret_cast<const float*>(
                smem + (((step - 1) & 1) ? SM_Z1 : SM_Z0));
            const float* zr = sz + row * ZSTR;

            float g0 = fgate(zr[0]);
            float ga = fgate(zr[1 + (j >> 1)]);
            float p1 = (j & 2) ? (1.0f - g0) : g0;
            float p2 = (j & 1) ? (1.0f - ga) : ga;
            float prod = p1 * p2;
            float acc = 0.0f;
            switch (j) {
                case 0:  walk<2, 3>(zr, spr, prod, acc); break;
                case 1:  walk<2, 4>(zr, spr, prod, acc); break;
                case 2:  walk<2, 5>(zr, spr, prod, acc); break;
                default: walk<2, 6>(zr, spr, prod, acc); break;
            }
            pbuf[etid] = acc;
            EPI_BAR();
            if (j == 0) {
                float s = (pbuf[row] + pbuf[row + 32]) +
                          (pbuf[row + 64] + pbuf[row + 96]);
                out[tile * ROWS_T + row] = s;
            }
        }
    }
}

// ---------------------------------------------------------------------------
extern "C" void kernel_launch(void* const* d_in, const int* in_sizes, int n_in,
                              void* d_out, int out_size) {
    const float* x   = (const float*)d_in[0];   // (N, 32)
    const float* fi  = (const float*)d_in[1];   // (255*32, 1)
    const float* fs  = (const float*)d_in[2];   // (255*32, 1)
    const float* cls = (const float*)d_in[3];   // (256, 1)
    float* out = (float*)d_out;                 // (N, 1) float32

    cudaFuncSetAttribute(dtree_kernel,
                         cudaFuncAttributeMaxDynamicSharedMemorySize, SM_TOTAL);
    prep_kernel<<<256, 32>>>(fi, fs, cls);
    dtree_kernel<<<NCTA, TPB, SM_TOTAL>>>(x, out);
}

// round 15
// speedup vs baseline: 1.9634x; 1.6348x over previous
#include <cuda_runtime.h>
#include <cstdint>

// DTree_84061099917446 — soft decision tree forward pass.
// N=262144 rows, F=32, depth 8, 255 nodes, 256 leaves, C=1.
//
// R15: warp-autonomous tiles — NO cross-warp synchronization in steady
// state. R10-R14's producer/consumer pipelines all stalled at ~158us with
// every pipe <30% (CTA-barrier lockstep burned ~5x the per-step work).
// Now each warp owns a 16-row x 256-col tile end-to-end: A direct from
// GMEM, bf16 3-pass m16n8k16 mma (rel_err 1.5e-6, R14-verified layout),
// z into a PRIVATE 16.4KB smem slice, __syncwarp, then a branch-free
// 2-threads-per-row tree walk (j-offset indexing, no divergence). 1184
// independent warps self-overlap each other's MMA / MUFU / DRAM phases.
// MUFU floor ~32us chip-wide.

#define F_        32
#define NODES_    255
#define N_ROWS    262144
#define TPB       128
#define NCTA      296
#define NWT       (N_ROWS / 16)          // 16384 warp-tiles
#define WARPS_TOT (NCTA * 4)             // 1184
#define LOG2E_F   1.4426950408889634f

typedef unsigned int u32;
typedef unsigned long long u64;

// ---- smem layout (byte offsets) ----
#define ZSTR      257                    // floats; odd -> conflict-free
#define ZWARP     (16 * ZSTR * 4)        // 16448 B per warp slice
#define SM_Z      0                      // 4 * 16448 = 65792
#define SM_BH     65792                  // 1024 float4 = 16384
#define SM_BL     82176                  // 16384
#define SM_BIAS   98560                  // 256 floats
#define SM_PR     99584                  // 128 float2
#define SM_TOTAL  100608                 // x2 CTAs = 201KB < 227KB

// Prologue outputs (scratch via __device__ globals — no allocation).
__device__ __align__(16) float4 g_Bh4[1024];   // B frags bf16x2 hi (mma order)
__device__ __align__(16) float4 g_Bl4[1024];   // B frags bf16x2 lo
__device__ float  g_bias[256];                 // +log2e*c (idx 255: 0)
__device__ float2 g_pr[128];                   // (clsR, clsL - clsR)

// ---------------------------------------------------------------------------
// split (x,y) -> bf16x2 hi (truncate) + bf16x2 lo (residual, rn)
__device__ __forceinline__ void split2(float vx, float vy, u32& hi, u32& lo) {
    u32 bx = __float_as_uint(vx), by = __float_as_uint(vy);
    hi = __byte_perm(bx, by, 0x7632);
    float lx = vx - __uint_as_float(bx & 0xFFFF0000u);
    float ly = vy - __uint_as_float(by & 0xFFFF0000u);
    asm("cvt.rn.bf16x2.f32 %0, %1, %2;" : "=r"(lo) : "f"(ly), "f"(lx));
}

// ---------------------------------------------------------------------------
// Prologue: 256 blocks x 32 threads; block n = node/column n (255 = pad).
// (R14-verified fragment layout.)
// ---------------------------------------------------------------------------
__global__ void prep_kernel(const float* __restrict__ fi,
                            const float* __restrict__ fs,
                            const float* __restrict__ cls) {
    __shared__ float sh[F_];
    int n = blockIdx.x;
    int f = threadIdx.x;
    float w = 0.0f, s = 0.0f;
    if (n < NODES_) {
        int idx = n * F_ + f;
        w = fmaxf(fi[idx], 0.0f);
        s = 1.0f / (1.0f + expf(-fs[idx]));
    }
    sh[f] = -LOG2E_F * w;
    float p = w * s;
    #pragma unroll
    for (int o = 16; o > 0; o >>= 1) p += __shfl_xor_sync(0xffffffffu, p, o);
    __syncwarp();
    if (f == 0) g_bias[n] = (n < NODES_) ? (LOG2E_F * p) : 0.0f;
    if (f < 4) {
        int tig = f;
        u32 qh[4], ql[4];
        #pragma unroll
        for (int s2 = 0; s2 < 2; ++s2)
            #pragma unroll
            for (int r = 0; r < 2; ++r) {
                int k = 16 * s2 + 8 * r + 2 * tig;
                split2(sh[k], sh[k + 1], qh[s2 * 2 + r], ql[s2 * 2 + r]);
            }
        int base = (n >> 3) * 32 + (n & 7) * 4 + tig;
        g_Bh4[base] = make_float4(__uint_as_float(qh[0]), __uint_as_float(qh[1]),
                                  __uint_as_float(qh[2]), __uint_as_float(qh[3]));
        g_Bl4[base] = make_float4(__uint_as_float(ql[0]), __uint_as_float(ql[1]),
                                  __uint_as_float(ql[2]), __uint_as_float(ql[3]));
    }
    if (n < 128 && f == 0) {
        float lv = cls[2 * n];
        float rv = cls[2 * n + 1];
        g_pr[n] = make_float2(rv, lv - rv);
    }
}

// ---------------------------------------------------------------------------
__device__ __forceinline__ void mma16(float (&d)[4], const u32* a,
                                      u32 b0, u32 b1) {
    asm volatile(
        "mma.sync.aligned.m16n8k16.row.col.f32.bf16.bf16.f32 "
        "{%0,%1,%2,%3}, {%4,%5,%6,%7}, {%8,%9}, {%0,%1,%2,%3};"
        : "+f"(d[0]), "+f"(d[1]), "+f"(d[2]), "+f"(d[3])
        : "r"(a[0]), "r"(a[1]), "r"(a[2]), "r"(a[3]), "r"(b0), "r"(b1));
}

__device__ __forceinline__ float fgate(float y) {   // 1 / (1 + 2^y)
    float e, g;
    asm("ex2.approx.f32 %0, %1;" : "=f"(e) : "f"(y));
    float d = 1.0f + e;
    asm("rcp.approx.f32 %0, %1;" : "=f"(g) : "f"(d));
    return g;
}

// ---------------------------------------------------------------------------
// Branch-free subtree walk. Both j=0 (left, root child 1) and j=1 (right,
// root child 2) execute the SAME instruction stream; the subtree is selected
// by a data offset: abs node at depth d, rel r = (2^d - 1) + j*2^(d-1) + r.
// ---------------------------------------------------------------------------
template<int DEPTH, int REL>
__device__ __forceinline__ void walk(const float*  __restrict__ zr,
                                     const float2* __restrict__ spr,
                                     int j, float prod, float& acc) {
    constexpr int BASE = (1 << DEPTH) - 1;
    constexpr int HALF = 1 << (DEPTH - 1);
    float g = fgate(zr[BASE + (j ? HALF : 0) + REL]);
    if constexpr (DEPTH == 7) {
        float2 pr = spr[(j ? 64 : 0) + REL];          // (clsR, clsL - clsR)
        acc = fmaf(prod, fmaf(g, pr.y, pr.x), acc);
    } else {
        float r = fmaf(-prod, g, prod);               // prod*(1-g)
        walk<DEPTH + 1, 2 * REL>(zr, spr, j, prod * g, acc);
        walk<DEPTH + 1, 2 * REL + 1>(zr, spr, j, r, acc);
    }
}

// ---------------------------------------------------------------------------
__global__ void __launch_bounds__(TPB, 2)
dtree_kernel(const float* __restrict__ x,
             float* __restrict__ out) {
    extern __shared__ __align__(16) char smem[];
    float4* sBh   = reinterpret_cast<float4*>(smem + SM_BH);
    float4* sBl   = reinterpret_cast<float4*>(smem + SM_BL);
    float*  sbias = reinterpret_cast<float*>(smem + SM_BIAS);
    float2* spr   = reinterpret_cast<float2*>(smem + SM_PR);

    int tid  = threadIdx.x;
    int lane = tid & 31;
    int wrp  = tid >> 5;
    float* szw = reinterpret_cast<float*>(smem + SM_Z + wrp * ZWARP);

    for (int i = tid; i < 1024; i += TPB) { sBh[i] = g_Bh4[i]; sBl[i] = g_Bl4[i]; }
    for (int i = tid; i < 256; i += TPB) sbias[i] = g_bias[i];
    if (tid < 128) spr[tid] = g_pr[tid];
    __syncthreads();                        // ONLY cta-wide sync in the kernel

    int gid = lane >> 2, tig = lane & 3;    // mma fragment coords
    int row = lane >> 1, j = lane & 1;      // walk coords: 2 threads per row

    for (int wt = blockIdx.x * 4 + wrp; wt < NWT; wt += WARPS_TOT) {
        // ---- A fragments: 16 rows straight from GMEM, split hi/lo ----
        const float2* xt2 = reinterpret_cast<const float2*>(x) + (size_t)wt * 256;
        u32 ah[8], al[8];
        {
            float2 v0[4], v1[4];
            #pragma unroll
            for (int s2 = 0; s2 < 2; ++s2)
                #pragma unroll
                for (int p = 0; p < 2; ++p) {
                    int kp = tig + 4 * p + 8 * s2;
                    int iv = s2 * 2 + p;
                    v0[iv] = __ldg(&xt2[gid * 16 + kp]);
                    v1[iv] = __ldg(&xt2[(gid + 8) * 16 + kp]);
                }
            #pragma unroll
            for (int s2 = 0; s2 < 2; ++s2)
                #pragma unroll
                for (int p = 0; p < 2; ++p) {
                    int ix = s2 * 4 + p * 2;
                    int iv = s2 * 2 + p;
                    split2(v0[iv].x, v0[iv].y, ah[ix],     al[ix]);
                    split2(v1[iv].x, v1[iv].y, ah[ix + 1], al[ix + 1]);
                }
        }

        // ---- GEMM: 32 column-groups x (2 LDS.128 + 6 MMA + STS) ----
        #pragma unroll 4
        for (int nt = 0; nt < 32; ++nt) {
            float4 h = sBh[nt * 32 + lane];
            float4 l = sBl[nt * 32 + lane];
            int c0 = nt * 8 + 2 * tig;
            float2 bi = *reinterpret_cast<const float2*>(sbias + c0);
            float d[4] = {bi.x, bi.y, bi.x, bi.y};
            float e[4] = {0.f, 0.f, 0.f, 0.f};
            mma16(d, &ah[0], __float_as_uint(h.x), __float_as_uint(h.y));
            mma16(e, &ah[0], __float_as_uint(l.x), __float_as_uint(l.y));
            mma16(e, &al[0], __float_as_uint(h.x), __float_as_uint(h.y));
            mma16(d, &ah[4], __float_as_uint(h.z), __float_as_uint(h.w));
            mma16(e, &ah[4], __float_as_uint(l.z), __float_as_uint(l.w));
            mma16(e, &al[4], __float_as_uint(h.z), __float_as_uint(h.w));
            float* z0 = szw + gid * ZSTR + c0;
            float* z1 = szw + (gid + 8) * ZSTR + c0;
            z0[0] = d[0] + e[0];
            z0[1] = d[1] + e[1];
            z1[0] = d[2] + e[2];
            z1[1] = d[3] + e[3];
        }
        __syncwarp();

        // ---- walk: 2 threads per row, branch-free subtree select ----
        {
            const float* zr = szw + row * ZSTR;
            float g0 = fgate(zr[0]);
            float p0 = j ? (1.0f - g0) : g0;
            float acc = 0.0f;
            walk<1, 0>(zr, spr, j, p0, acc);
            float other = __shfl_xor_sync(0xffffffffu, acc, 1);
            if (j == 0) out[wt * 16 + row] = acc + other;
        }
        __syncwarp();                       // z reads done before next STS
    }
}

// ---------------------------------------------------------------------------
extern "C" void kernel_launch(void* const* d_in, const int* in_sizes, int n_in,
                              void* d_out, int out_size) {
    const float* x   = (const float*)d_in[0];   // (N, 32)
    const float* fi  = (const float*)d_in[1];   // (255*32, 1)
    const float* fs  = (const float*)d_in[2];   // (255*32, 1)
    const float* cls = (const float*)d_in[3];   // (256, 1)
    float* out = (float*)d_out;                 // (N, 1) float32

    cudaFuncSetAttribute(dtree_kernel,
                         cudaFuncAttributeMaxDynamicSharedMemorySize, SM_TOTAL);
    prep_kernel<<<256, 32>>>(fi, fs, cls);
    dtree_kernel<<<NCTA, TPB, SM_TOTAL>>>(x, out);
}

// round 17
// speedup vs baseline: 2.1507x; 1.0954x over previous
#include <cuda_runtime.h>
#include <cstdint>

// DTree_84061099917446 — soft decision tree forward pass.
// N=262144 rows, F=32, depth 8, 255 nodes, 256 leaves, C=1.
//
// R17 (= R16 with the misalignment fixed): R16's STS.64 z-stores trapped —
// ZSTR=261 (odd) makes odd rows' float2 addresses 4B-aligned only. Revert
// z-stores to scalar STS.32 (R15 style); keep everything else from R16:
//  - ZSTR 261 (stride 5 mod 32) + node->column permutation with
//    colR - colL = 16 (mod 32) per depth => walk LDS conflict-free
//    (banks {5r} vs {5r+16} disjoint; verified for all 7 depths).
//  - A prefetch: next tile's LDGs issue before the walk (latency hidden).
//  - per-depth walk base pointers (j folded in, zero per-node ALU).
// GEMM: bf16 3-pass m16n8k16 (rel_err 1.5e-6), B frags + bias from smem.

#define F_        32
#define NODES_    255
#define N_ROWS    262144
#define TPB       128
#define NCTA      296
#define NWT       (N_ROWS / 16)          // 16384 warp-tiles
#define WARPS_TOT (NCTA * 4)             // 1184
#define LOG2E_F   1.4426950408889634f

typedef unsigned int u32;

// ---- column layout: per-depth left/right block bases ----
//                         d:   0    1    2    3    4    5    6   7
__device__ __constant__ int c_LB[8] = {79,  78,  76,  72, 240, 176, 144,  0};
__device__ __constant__ int c_RB[8] = {79, 254, 252, 248,  64, 224, 192, 80};

// ---- smem layout (byte offsets) ----
#define ZSTR      261                    // floats; 261 mod 32 = 5
#define ZWARP     (16 * ZSTR * 4)        // 16704 B per warp slice
#define SM_Z      0                      // 4 * 16704 = 66816
#define SM_BH     66816                  // 1024 float4 = 16384
#define SM_BL     83200                  // 16384
#define SM_BIAS   99584                  // 256 floats
#define SM_PR     100608                 // 128 float2 = 1024
#define SM_TOTAL  101632                 // x2 CTAs = 203KB < 227KB

// Prologue outputs (scratch via __device__ globals — no allocation).
__device__ __align__(16) float4 g_Bh4[1024];   // B frags bf16x2 hi (col order)
__device__ __align__(16) float4 g_Bl4[1024];   // B frags bf16x2 lo
__device__ float  g_bias[256];                 // +log2e*c at column slots
__device__ float2 g_pr[128];                   // (clsR, clsL - clsR)

// ---------------------------------------------------------------------------
// split (x,y) -> bf16x2 hi (truncate) + bf16x2 lo (residual, rn)
__device__ __forceinline__ void split2(float vx, float vy, u32& hi, u32& lo) {
    u32 bx = __float_as_uint(vx), by = __float_as_uint(vy);
    hi = __byte_perm(bx, by, 0x7632);
    float lx = vx - __uint_as_float(bx & 0xFFFF0000u);
    float ly = vy - __uint_as_float(by & 0xFFFF0000u);
    asm("cvt.rn.bf16x2.f32 %0, %1, %2;" : "=r"(lo) : "f"(ly), "f"(lx));
}

// ---------------------------------------------------------------------------
// Prologue: 256 blocks x 32 threads; block n = tree node n (255 = pad).
// Writes node n's fragments / bias at its assigned GEMM COLUMN.
// ---------------------------------------------------------------------------
__global__ void prep_kernel(const float* __restrict__ fi,
                            const float* __restrict__ fs,
                            const float* __restrict__ cls) {
    __shared__ float sh[F_];
    int n = blockIdx.x;
    int f = threadIdx.x;
    float w = 0.0f, s = 0.0f;
    if (n < NODES_) {
        int idx = n * F_ + f;
        w = fmaxf(fi[idx], 0.0f);
        s = 1.0f / (1.0f + expf(-fs[idx]));
    }
    sh[f] = -LOG2E_F * w;
    float p = w * s;
    #pragma unroll
    for (int o = 16; o > 0; o >>= 1) p += __shfl_xor_sync(0xffffffffu, p, o);
    __syncwarp();

    // column assignment for node n
    int col;
    if (n >= NODES_) {
        col = 255;                         // pad slot
    } else {
        int v = n + 1;
        int d = 31 - __clz(v);             // depth 0..7
        if (d == 0) col = 79;
        else {
            int q    = v - (1 << d);
            int half = 1 << (d - 1);
            int j    = q >> (d - 1);
            int rel  = q & (half - 1);
            col = (j ? c_RB[d] : c_LB[d]) + rel;
        }
    }

    if (f == 0) g_bias[col] = (n < NODES_) ? (LOG2E_F * p) : 0.0f;
    if (f < 4) {
        int tig = f;
        u32 qh[4], ql[4];
        #pragma unroll
        for (int s2 = 0; s2 < 2; ++s2)
            #pragma unroll
            for (int r = 0; r < 2; ++r) {
                int k = 16 * s2 + 8 * r + 2 * tig;
                split2(sh[k], sh[k + 1], qh[s2 * 2 + r], ql[s2 * 2 + r]);
            }
        int base = (col >> 3) * 32 + (col & 7) * 4 + tig;
        g_Bh4[base] = make_float4(__uint_as_float(qh[0]), __uint_as_float(qh[1]),
                                  __uint_as_float(qh[2]), __uint_as_float(qh[3]));
        g_Bl4[base] = make_float4(__uint_as_float(ql[0]), __uint_as_float(ql[1]),
                                  __uint_as_float(ql[2]), __uint_as_float(ql[3]));
    }
    if (n < 128 && f == 0) {
        float lv = cls[2 * n];
        float rv = cls[2 * n + 1];
        g_pr[n] = make_float2(rv, lv - rv);
    }
}

// ---------------------------------------------------------------------------
__device__ __forceinline__ void mma16(float (&d)[4], const u32* a,
                                      u32 b0, u32 b1) {
    asm volatile(
        "mma.sync.aligned.m16n8k16.row.col.f32.bf16.bf16.f32 "
        "{%0,%1,%2,%3}, {%4,%5,%6,%7}, {%8,%9}, {%0,%1,%2,%3};"
        : "+f"(d[0]), "+f"(d[1]), "+f"(d[2]), "+f"(d[3])
        : "r"(a[0]), "r"(a[1]), "r"(a[2]), "r"(a[3]), "r"(b0), "r"(b1));
}

__device__ __forceinline__ float fgate(float y) {   // 1 / (1 + 2^y)
    float e, g;
    asm("ex2.approx.f32 %0, %1;" : "=f"(e) : "f"(y));
    float d = 1.0f + e;
    asm("rcp.approx.f32 %0, %1;" : "=f"(g) : "f"(d));
    return g;
}

// ---------------------------------------------------------------------------
// Walk with per-depth base pointers (column layout pre-resolved, j folded in).
// bp[d] = zr + (j ? RB[d] : LB[d]); node at (DEPTH, REL) reads bp[DEPTH][REL].
// ---------------------------------------------------------------------------
template<int DEPTH, int REL>
__device__ __forceinline__ void walk(const float* const (&bp)[8],
                                     const float2* __restrict__ sp,
                                     float prod, float& acc) {
    float g = fgate(bp[DEPTH][REL]);
    if constexpr (DEPTH == 7) {
        float2 pr = sp[REL];                  // (clsR, clsL - clsR)
        acc = fmaf(prod, fmaf(g, pr.y, pr.x), acc);
    } else {
        float r = fmaf(-prod, g, prod);       // prod*(1-g)
        walk<DEPTH + 1, 2 * REL>(bp, sp, prod * g, acc);
        walk<DEPTH + 1, 2 * REL + 1>(bp, sp, r, acc);
    }
}

// ---------------------------------------------------------------------------
__global__ void __launch_bounds__(TPB, 2)
dtree_kernel(const float* __restrict__ x,
             float* __restrict__ out) {
    extern __shared__ __align__(16) char smem[];
    float4* sBh   = reinterpret_cast<float4*>(smem + SM_BH);
    float4* sBl   = reinterpret_cast<float4*>(smem + SM_BL);
    float*  sbias = reinterpret_cast<float*>(smem + SM_BIAS);
    float2* spr   = reinterpret_cast<float2*>(smem + SM_PR);

    int tid  = threadIdx.x;
    int lane = tid & 31;
    int wrp  = tid >> 5;
    float* szw = reinterpret_cast<float*>(smem + SM_Z + wrp * ZWARP);

    for (int i = tid; i < 1024; i += TPB) { sBh[i] = g_Bh4[i]; sBl[i] = g_Bl4[i]; }
    for (int i = tid; i < 256; i += TPB) sbias[i] = g_bias[i];
    if (tid < 128) spr[tid] = g_pr[tid];
    __syncthreads();                        // only CTA-wide sync

    int gid = lane >> 2, tig = lane & 3;    // mma fragment coords
    int row = lane >> 1, j = lane & 1;      // walk coords

    // per-depth walk base pointers (j folded in; constant per thread)
    const float* zr = szw + row * ZSTR;
    const float* bp[8];
    #pragma unroll
    for (int d = 1; d < 8; ++d) bp[d] = zr + (j ? c_RB[d] : c_LB[d]);
    bp[0] = zr;                              // unused
    const float2* spj = spr + (j ? 64 : 0);

    int wt0 = blockIdx.x * 4 + wrp;

    // prologue A load for first tile
    float2 v[8];
    {
        const float2* xt2 = reinterpret_cast<const float2*>(x) + (size_t)wt0 * 256;
        #pragma unroll
        for (int s2 = 0; s2 < 2; ++s2)
            #pragma unroll
            for (int p = 0; p < 2; ++p) {
                int kp = tig + 4 * p + 8 * s2;
                int iv = s2 * 2 + p;
                v[iv]     = __ldg(&xt2[gid * 16 + kp]);
                v[4 + iv] = __ldg(&xt2[(gid + 8) * 16 + kp]);
            }
    }

    for (int wt = wt0; wt < NWT; wt += WARPS_TOT) {
        // ---- split prefetched A into bf16 hi/lo fragments ----
        u32 ah[8], al[8];
        #pragma unroll
        for (int s2 = 0; s2 < 2; ++s2)
            #pragma unroll
            for (int p = 0; p < 2; ++p) {
                int ix = s2 * 4 + p * 2;
                int iv = s2 * 2 + p;
                split2(v[iv].x,     v[iv].y,     ah[ix],     al[ix]);
                split2(v[4 + iv].x, v[4 + iv].y, ah[ix + 1], al[ix + 1]);
            }

        // ---- GEMM: 32 col-groups x (2 LDS.128 + 6 MMA + 4 STS.32) ----
        #pragma unroll 4
        for (int nt = 0; nt < 32; ++nt) {
            float4 h = sBh[nt * 32 + lane];
            float4 l = sBl[nt * 32 + lane];
            int c0 = nt * 8 + 2 * tig;
            float2 bi = *reinterpret_cast<const float2*>(sbias + c0);
            float d[4] = {bi.x, bi.y, bi.x, bi.y};
            float e[4] = {0.f, 0.f, 0.f, 0.f};
            mma16(d, &ah[0], __float_as_uint(h.x), __float_as_uint(h.y));
            mma16(e, &ah[0], __float_as_uint(l.x), __float_as_uint(l.y));
            mma16(e, &al[0], __float_as_uint(h.x), __float_as_uint(h.y));
            mma16(d, &ah[4], __float_as_uint(h.z), __float_as_uint(h.w));
            mma16(e, &ah[4], __float_as_uint(l.z), __float_as_uint(l.w));
            mma16(e, &al[4], __float_as_uint(h.z), __float_as_uint(h.w));
            float* z0 = szw + gid * ZSTR + c0;          // scalar stores:
            float* z1 = szw + (gid + 8) * ZSTR + c0;    // 4B-aligned always
            z0[0] = d[0] + e[0];
            z0[1] = d[1] + e[1];
            z1[0] = d[2] + e[2];
            z1[1] = d[3] + e[3];
        }

        // ---- prefetch next tile's A (latency hidden under walk) ----
        {
            int nwt = wt + WARPS_TOT;
            if (nwt >= NWT) nwt = wt;        // dead (clamped) on last iter
            const float2* xt2 =
                reinterpret_cast<const float2*>(x) + (size_t)nwt * 256;
            #pragma unroll
            for (int s2 = 0; s2 < 2; ++s2)
                #pragma unroll
                for (int p = 0; p < 2; ++p) {
                    int kp = tig + 4 * p + 8 * s2;
                    int iv = s2 * 2 + p;
                    v[iv]     = __ldg(&xt2[gid * 16 + kp]);
                    v[4 + iv] = __ldg(&xt2[(gid + 8) * 16 + kp]);
                }
        }
        __syncwarp();

        // ---- walk: 2 threads per row, conflict-free z reads ----
        {
            float g0 = fgate(zr[79]);            // root column
            float p0 = j ? (1.0f - g0) : g0;
            float acc = 0.0f;
            walk<1, 0>(bp, spj, p0, acc);
            float other = __shfl_xor_sync(0xffffffffu, acc, 1);
            if (j == 0) out[wt * 16 + row] = acc + other;
        }
        __syncwarp();                            // z reads done before next STS
    }
}

// ---------------------------------------------------------------------------
extern "C" void kernel_launch(void* const* d_in, const int* in_sizes, int n_in,
                              void* d_out, int out_size) {
    const float* x   = (const float*)d_in[0];   // (N, 32)
    const float* fi  = (const float*)d_in[1];   // (255*32, 1)
    const float* fs  = (const float*)d_in[2];   // (255*32, 1)
    const float* cls = (const float*)d_in[3];   // (256, 1)
    float* out = (float*)d_out;                 // (N, 1) float32

    cudaFuncSetAttribute(dtree_kernel,
                         cudaFuncAttributeMaxDynamicSharedMemorySize, SM_TOTAL);
    prep_kernel<<<256, 32>>>(fi, fs, cls);
    dtree_kernel<<<NCTA, TPB, SM_TOTAL>>>(x, out);
}